// round 13
// baseline (speedup 1.0000x reference)
#include <cuda_runtime.h>
#include <cuda_bf16.h>
#include <cstdint>

#define B_    4096
#define FIN   64
#define NK    512
#define FOUT  256
#define TB    16
#define NTHR  256
#define AP    24            // A pitch in b32: banks 24*tig+g all distinct
#define XRP   68            // staged x pitch (floats)

typedef unsigned long long ull;

__device__ float    g_cc[NK];
__device__ float    g_s2[NK];
__device__ uint32_t g_Wpk[131072];   // 512KB: phase-3 B fragments, register order
__device__ uint4    g_Cpk[8192];     // 128KB: phase-1 B fragments (centers split-bf16)

// ---- smem (u32 offsets) ----
#define SM_A    0               // [512 kp_eff][AP], 16 rows used: kp 0-255 hi, 256-511 lo
#define SM_XR   12288           // staged x [16][XRP]
#define SM_XF   13376           // x fragments: 8 frags x 32 lanes x uint4
#define SM_PART 14400           // [8 warps][16 rows]
#define SM_INV  14528
#define SM_XX   14544
#define SM_CC   14560
#define SM_S2   15072
#define SM_TOT  15584
#define SMEM_BYTES (SM_TOT * 4) // ~61 KB -> 2 CTAs/SM

__device__ __forceinline__ uint32_t pack_bf2(__nv_bfloat16 a, __nv_bfloat16 b) {
    __nv_bfloat162 t; t.x = a; t.y = b;
    return *reinterpret_cast<uint32_t*>(&t);
}
__device__ __forceinline__ uint32_t split_hi(float a, float b) {
    return pack_bf2(__float2bfloat16(a), __float2bfloat16(b));
}
__device__ __forceinline__ uint32_t split_lo(float a, float b) {
    __nv_bfloat16 ha = __float2bfloat16(a), hb = __float2bfloat16(b);
    return pack_bf2(__float2bfloat16(a - __bfloat162float(ha)),
                    __float2bfloat16(b - __bfloat162float(hb)));
}

#define MMA16816(D,a0,a1,a2,a3,b0,b1) \
    asm("mma.sync.aligned.m16n8k16.row.col.f32.bf16.bf16.f32 " \
        "{%0,%1,%2,%3}, {%4,%5,%6,%7}, {%8,%9}, {%0,%1,%2,%3};" \
        : "+f"(D[0]), "+f"(D[1]), "+f"(D[2]), "+f"(D[3]) \
        : "r"(a0), "r"(a1), "r"(a2), "r"(a3), "r"(b0), "r"(b1))

// -------- prep: stats, W pack (coalesced reads), centers pack --------
__global__ void prep_all(const float* __restrict__ W,
                         const float* __restrict__ centers,
                         const float* __restrict__ ls) {
    int bid = blockIdx.x;
    if (bid < 16) {
        int kb = bid * 32;
        int warp = threadIdx.x >> 5, lane = threadIdx.x & 31;
        #pragma unroll
        for (int c = warp; c < 32; c += 8) {
            int k = kb + c;
            float v0 = centers[k * FIN + lane];
            float v1 = centers[k * FIN + 32 + lane];
            float s = fmaf(v0, v0, v1 * v1);
            #pragma unroll
            for (int off = 16; off; off >>= 1) s += __shfl_xor_sync(0xffffffffu, s, off);
            if (lane == 0) g_cc[k] = s;
        }
        if (threadIdx.x < 32) g_s2[kb + threadIdx.x] = __expf(2.f * ls[kb + threadIdx.x]);
    } else if (bid < 528) {
        // W pack, coalesced reads: thread <- (split, col, kpair)
        int q = (bid - 16) * 256 + threadIdx.x;   // 0..131071
        int split = q >> 16;
        int rem   = q & 65535;
        int col   = rem >> 8;
        int kp2   = rem & 255;
        float2 wv = *(const float2*)(W + (size_t)col * NK + 2 * kp2);
        int h   = split * 8 + (kp2 >> 5);
        int kl  = kp2 & 31;
        int tig = kl & 3, ki = (kl >> 2) & 1, ks = kl >> 3;
        int g   = col & 7, t = (col >> 3) & 3, wn = col >> 5;
        int j   = 2 * t + ki, half = j >> 2, jp = j & 3;
        int lane = g * 4 + tig;
        int qo = jp | (lane << 2) | (half << 7) | (ks << 8) | (wn << 10) | (h << 13);
        g_Wpk[qo] = split ? split_lo(wv.x, wv.y) : split_hi(wv.x, wv.y);
    } else {
        // phase-1 centers pack (verified R9 layout)
        int q = (bid - 528) * 256 + threadIdx.x;   // 0..8191
        int lane = q & 31;
        int tp   = (q >> 5) & 1;
        int phys = (q >> 6) & 7;
        int w    = q >> 9;
        int g    = lane >> 2;
        int tig  = lane & 3;
        int ks   = phys & 3;
        bool lo  = phys >= 4;
        int colA = w * 32 + (2 * tp) * 8 + g;
        int colB = colA + 8;
        int k0   = 16 * ks + 2 * tig;
        int k1   = k0 + 8;
        const float* cA = centers + (size_t)colA * FIN;
        const float* cB = centers + (size_t)colB * FIN;
        float2 a0 = *(const float2*)(cA + k0);
        float2 a1 = *(const float2*)(cA + k1);
        float2 b0 = *(const float2*)(cB + k0);
        float2 b1 = *(const float2*)(cB + k1);
        uint4 r;
        if (lo) {
            r.x = split_lo(a0.x, a0.y); r.y = split_lo(a1.x, a1.y);
            r.z = split_lo(b0.x, b0.y); r.w = split_lo(b1.x, b1.y);
        } else {
            r.x = split_hi(a0.x, a0.y); r.y = split_hi(a1.x, a1.y);
            r.z = split_hi(b0.x, b0.y); r.w = split_hi(b1.x, b1.y);
        }
        g_Cpk[q] = r;
    }
}

// -------- fused main kernel: 256 thr, TB=16 rows, grid 256, 2 CTAs/SM --------
__global__ __launch_bounds__(NTHR, 2)
void rbf_main(const float* __restrict__ x,
              float* __restrict__ out) {
    extern __shared__ float sm[];
    uint32_t* A32 = (uint32_t*)sm;
    const int tid  = threadIdx.x;
    const int lane = tid & 31;
    const int warp = tid >> 5;          // 0..7
    const int g    = lane >> 2;
    const int tig  = lane & 3;
    const int b0   = blockIdx.x * TB;

    // ---- stage 1: coalesced x tile load (16 rows) + per-k constants ----
    sm[SM_CC + tid]       = g_cc[tid];
    sm[SM_CC + tid + 256] = g_cc[tid + 256];
    sm[SM_S2 + tid]       = g_s2[tid];
    sm[SM_S2 + tid + 256] = g_s2[tid + 256];
    {
        const float4* x4 = (const float4*)(x + (size_t)b0 * FIN);
        int r = tid >> 4, c = tid & 15;
        *(float4*)&sm[SM_XR + r * XRP + c * 4] = __ldg(x4 + tid);
    }
    __syncthreads();

    // ---- stage 2a: ||x||^2 (warp w handles rows 2w, 2w+1; 16 lanes each) ----
    {
        int row = 2 * warp + (lane >> 4);
        float4 v = *(const float4*)&sm[SM_XR + row * XRP + (lane & 15) * 4];
        float s = fmaf(v.x, v.x, v.y * v.y) + fmaf(v.z, v.z, v.w * v.w);
        s += __shfl_xor_sync(0xffffffffu, s, 1);
        s += __shfl_xor_sync(0xffffffffu, s, 2);
        s += __shfl_xor_sync(0xffffffffu, s, 4);
        s += __shfl_xor_sync(0xffffffffu, s, 8);
        if ((lane & 15) == 0) sm[SM_XX + row] = s;
    }
    // ---- stage 2b: build shared x fragments (8 frags; tid -> one uint4) ----
    {
        int fid = tid >> 5;                 // 0..7: ks = fid>>1, sp = fid&1
        int gg  = (tid >> 2) & 7;
        int tt  = tid & 3;
        int ks = fid >> 1, sp = fid & 1;
        int col0 = 16 * ks + 2 * tt;
        float2 u0 = *(const float2*)&sm[SM_XR + gg * XRP + col0];
        float2 u1 = *(const float2*)&sm[SM_XR + (gg + 8) * XRP + col0];
        float2 u2 = *(const float2*)&sm[SM_XR + gg * XRP + col0 + 8];
        float2 u3 = *(const float2*)&sm[SM_XR + (gg + 8) * XRP + col0 + 8];
        uint4 fr;
        if (sp) {
            fr.x = split_lo(u0.x, u0.y); fr.y = split_lo(u1.x, u1.y);
            fr.z = split_lo(u2.x, u2.y); fr.w = split_lo(u3.x, u3.y);
        } else {
            fr.x = split_hi(u0.x, u0.y); fr.y = split_hi(u1.x, u1.y);
            fr.z = split_hi(u2.x, u2.y); fr.w = split_hi(u3.x, u3.y);
        }
        ((uint4*)((uint32_t*)sm + SM_XF))[tid] = fr;
    }
    __syncthreads();

    // ---- phase 1: warp covers cols [64w, 64w+64) in two 32-col passes ----
    const uint4* XFv = (const uint4*)((uint32_t*)sm + SM_XF);
    float psum0 = 0.f, psum1 = 0.f;

    #pragma unroll
    for (int p = 0; p < 2; p++) {
        const int wcol = 2 * warp + p;      // 32-col group 0..15
        float acc[4][4];
        #pragma unroll
        for (int nt = 0; nt < 4; nt++)
            #pragma unroll
            for (int i = 0; i < 4; i++) acc[nt][i] = 0.f;

        const uint4* cp = g_Cpk + (size_t)wcol * 512;
        #pragma unroll
        for (int ks = 0; ks < 4; ks++) {
            uint4 bh0 = __ldg(cp + (ks * 2 + 0) * 32 + lane);
            uint4 bh1 = __ldg(cp + (ks * 2 + 1) * 32 + lane);
            uint4 bl0 = __ldg(cp + ((4 + ks) * 2 + 0) * 32 + lane);
            uint4 bl1 = __ldg(cp + ((4 + ks) * 2 + 1) * 32 + lane);
            uint4 ah = XFv[(ks * 2 + 0) * 32 + lane];
            uint4 al = XFv[(ks * 2 + 1) * 32 + lane];
            MMA16816(acc[0], ah.x, ah.y, ah.z, ah.w, bh0.x, bh0.y);
            MMA16816(acc[1], ah.x, ah.y, ah.z, ah.w, bh0.z, bh0.w);
            MMA16816(acc[2], ah.x, ah.y, ah.z, ah.w, bh1.x, bh1.y);
            MMA16816(acc[3], ah.x, ah.y, ah.z, ah.w, bh1.z, bh1.w);
            MMA16816(acc[0], ah.x, ah.y, ah.z, ah.w, bl0.x, bl0.y);
            MMA16816(acc[1], ah.x, ah.y, ah.z, ah.w, bl0.z, bl0.w);
            MMA16816(acc[2], ah.x, ah.y, ah.z, ah.w, bl1.x, bl1.y);
            MMA16816(acc[3], ah.x, ah.y, ah.z, ah.w, bl1.z, bl1.w);
            MMA16816(acc[0], al.x, al.y, al.z, al.w, bh0.x, bh0.y);
            MMA16816(acc[1], al.x, al.y, al.z, al.w, bh0.z, bh0.w);
            MMA16816(acc[2], al.x, al.y, al.z, al.w, bh1.x, bh1.y);
            MMA16816(acc[3], al.x, al.y, al.z, al.w, bh1.z, bh1.w);
        }

        // epilogue for this 32-col pass: r2 -> exp -> A-tile + psum
        const float xx0 = sm[SM_XX + g];
        const float xx1 = sm[SM_XX + g + 8];
        #pragma unroll
        for (int nt = 0; nt < 4; nt++) {
            const int colp = wcol * 32 + nt * 8 + 2 * tig;
            const int kp   = colp >> 1;
            const float cc0 = sm[SM_CC + colp], cc1 = sm[SM_CC + colp + 1];
            const float s20 = sm[SM_S2 + colp], s21 = sm[SM_S2 + colp + 1];
            float r2, v00, v01, v10, v11;
            r2 = fmaf(-2.f, acc[nt][0], xx0 + cc0); v00 = __expf(-s20 * r2);
            r2 = fmaf(-2.f, acc[nt][1], xx0 + cc1); v01 = __expf(-s21 * r2);
            r2 = fmaf(-2.f, acc[nt][2], xx1 + cc0); v10 = __expf(-s20 * r2);
            r2 = fmaf(-2.f, acc[nt][3], xx1 + cc1); v11 = __expf(-s21 * r2);
            psum0 += v00 + v01;
            psum1 += v10 + v11;
            A32[(kp      ) * AP + g    ] = split_hi(v00, v01);
            A32[(kp      ) * AP + g + 8] = split_hi(v10, v11);
            A32[(kp + 256) * AP + g    ] = split_lo(v00, v01);
            A32[(kp + 256) * AP + g + 8] = split_lo(v10, v11);
        }
    }
    psum0 += __shfl_xor_sync(0xffffffffu, psum0, 1);
    psum0 += __shfl_xor_sync(0xffffffffu, psum0, 2);
    psum1 += __shfl_xor_sync(0xffffffffu, psum1, 1);
    psum1 += __shfl_xor_sync(0xffffffffu, psum1, 2);
    if (tig == 0) {
        sm[SM_PART + warp * 16 + g    ] = psum0;
        sm[SM_PART + warp * 16 + g + 8] = psum1;
    }
    __syncthreads();

    if (tid < 16) {
        float t = 1e-9f;
        #pragma unroll
        for (int w = 0; w < 8; w++) t += sm[SM_PART + w * 16 + tid];
        sm[SM_INV + tid] = 1.f / t;
    }
    __syncthreads();

    // ---- phase 3: warp = M16 x N32 (wn = warp); nested loops, B LDG ring ----
    const int wn = warp;

    float pacc[4][4];
    #pragma unroll
    for (int t = 0; t < 4; t++)
        #pragma unroll
        for (int i = 0; i < 4; i++) pacc[t][i] = 0.f;

    const uint4* bsrc = (const uint4*)g_Wpk;
    const uint32_t* Ab = A32 + g;
    int base = wn * 256 + lane;            // uint4 index of chunk 0, ks 0
    uint4 bA[4], bB[4];
    #pragma unroll
    for (int ks = 0; ks < 4; ks++) {
        bA[ks] = __ldg(bsrc + base + ks * 64);
        bB[ks] = __ldg(bsrc + base + ks * 64 + 32);
    }

    // loop 1: chunks 0-7 (W_hi) — R_hi and R_lo
    for (int c = 0; c < 8; c++) {
        const uint32_t* Ak = Ab + c * 32 * AP;
        #pragma unroll
        for (int ks = 0; ks < 4; ks++) {
            uint4 ba = bA[ks], bb = bB[ks];
            const int nix = base + 2048 + ks * 64;
            bA[ks] = __ldg(bsrc + nix);
            bB[ks] = __ldg(bsrc + nix + 32);
            const int kro = (ks * 8 + tig) * AP;
            uint32_t h0 = Ak[kro];
            uint32_t h1 = Ak[kro + 8];
            uint32_t h2 = Ak[kro + 4 * AP];
            uint32_t h3 = Ak[kro + 4 * AP + 8];
            MMA16816(pacc[0], h0, h1, h2, h3, ba.x, ba.y);
            MMA16816(pacc[1], h0, h1, h2, h3, ba.z, ba.w);
            MMA16816(pacc[2], h0, h1, h2, h3, bb.x, bb.y);
            MMA16816(pacc[3], h0, h1, h2, h3, bb.z, bb.w);
            uint32_t l0 = Ak[kro + 256 * AP];
            uint32_t l1 = Ak[kro + 256 * AP + 8];
            uint32_t l2 = Ak[kro + 260 * AP];
            uint32_t l3 = Ak[kro + 260 * AP + 8];
            MMA16816(pacc[0], l0, l1, l2, l3, ba.x, ba.y);
            MMA16816(pacc[1], l0, l1, l2, l3, ba.z, ba.w);
            MMA16816(pacc[2], l0, l1, l2, l3, bb.x, bb.y);
            MMA16816(pacc[3], l0, l1, l2, l3, bb.z, bb.w);
        }
        base += 2048;
    }
    // loop 2: chunks 8-15 (W_lo) — R_hi only
    for (int c = 0; c < 8; c++) {
        const uint32_t* Ak = Ab + c * 32 * AP;
        #pragma unroll
        for (int ks = 0; ks < 4; ks++) {
            uint4 ba = bA[ks], bb = bB[ks];
            if (c < 7) {
                const int nix = base + 2048 + ks * 64;
                bA[ks] = __ldg(bsrc + nix);
                bB[ks] = __ldg(bsrc + nix + 32);
            }
            const int kro = (ks * 8 + tig) * AP;
            uint32_t h0 = Ak[kro];
            uint32_t h1 = Ak[kro + 8];
            uint32_t h2 = Ak[kro + 4 * AP];
            uint32_t h3 = Ak[kro + 4 * AP + 8];
            MMA16816(pacc[0], h0, h1, h2, h3, ba.x, ba.y);
            MMA16816(pacc[1], h0, h1, h2, h3, ba.z, ba.w);
            MMA16816(pacc[2], h0, h1, h2, h3, bb.x, bb.y);
            MMA16816(pacc[3], h0, h1, h2, h3, bb.z, bb.w);
        }
        base += 2048;
    }

    // ---- epilogue: normalize + store ----
    const float i0 = sm[SM_INV + g];
    const float i1 = sm[SM_INV + g + 8];
    #pragma unroll
    for (int t = 0; t < 4; t++) {
        const int col = wn * 32 + t * 8 + tig * 2;
        *(float2*)(out + (size_t)(b0 + g) * FOUT + col) =
            make_float2(pacc[t][0] * i0, pacc[t][1] * i0);
        *(float2*)(out + (size_t)(b0 + g + 8) * FOUT + col) =
            make_float2(pacc[t][2] * i1, pacc[t][3] * i1);
    }
}

// -------- launch --------
extern "C" void kernel_launch(void* const* d_in, const int* in_sizes, int n_in,
                              void* d_out, int out_size) {
    const float* x       = (const float*)d_in[0];  // [4096, 64]
    const float* W       = (const float*)d_in[1];  // [256, 512]
    const float* centers = (const float*)d_in[2];  // [512, 64]
    const float* ls      = (const float*)d_in[3];  // [512]
    float* out = (float*)d_out;                    // [4096, 256]

    cudaFuncSetAttribute(rbf_main, cudaFuncAttributeMaxDynamicSharedMemorySize, SMEM_BYTES);

    prep_all<<<16 + 512 + 32, 256>>>(W, centers, ls);
    rbf_main<<<B_ / TB, NTHR, SMEM_BYTES>>>(x, out);
}